// round 8
// baseline (speedup 1.0000x reference)
#include <cuda_runtime.h>
#include <math.h>

// Problem constants (StatsSelect: B=32, C=512, T=4000, BR=2)
#define BB   32
#define CC   512
#define TT   4000
#define H4   2048          // 4*C stats features
#define NROW (BB * CC)     // 16384 rows
#define T4   (TT / 4)      // 1000 float4 per row

// Scratch (no cudaMalloc allowed)
__device__ float g_stats[BB * H4];   // [B, 4C]: mean | std | skew | kurt
__device__ float g_h[BB * CC];       // hidden   [B, C]
__device__ float g_gate[BB * CC];    // gate (branch-0 weight) per (b,c)

// ---------------------------------------------------------------------------
// Kernel 1: per-row raw moments of (x_a + x_b) over T, then HOS stats.
// ONE WARP PER ROW, no __syncthreads, no cross-warp reduce. Each lane streams
// 31-32 float4 from xa and xb (same loop shape as k_out, which hits 85% DRAM),
// then a warp-shuffle reduce + lane-0 epilogue. Warps are fully independent,
// so streaming and epilogue phases of different warps overlap -> HBM pipe
// stays fed (fixes the per-block duty-cycle loss of the previous version).
// ---------------------------------------------------------------------------
__global__ __launch_bounds__(256) void k_stats(const float* __restrict__ xa,
                                               const float* __restrict__ xb)
{
    const int row  = (blockIdx.x << 3) + (threadIdx.x >> 5);  // 8 warps/block
    const int lane = threadIdx.x & 31;

    const float4* a4 = reinterpret_cast<const float4*>(xa) + (size_t)row * T4;
    const float4* b4 = reinterpret_cast<const float4*>(xb) + (size_t)row * T4;

    float s1 = 0.f, s2 = 0.f, s3 = 0.f, s4 = 0.f;
    #pragma unroll 4
    for (int i = lane; i < T4; i += 32) {
        const float4 a = __ldg(a4 + i);
        const float4 b = __ldg(b4 + i);
        float v, v2;
        v = a.x + b.x; v2 = v * v; s1 += v; s2 += v2; s3 += v2 * v; s4 += v2 * v2;
        v = a.y + b.y; v2 = v * v; s1 += v; s2 += v2; s3 += v2 * v; s4 += v2 * v2;
        v = a.z + b.z; v2 = v * v; s1 += v; s2 += v2; s3 += v2 * v; s4 += v2 * v2;
        v = a.w + b.w; v2 = v * v; s1 += v; s2 += v2; s3 += v2 * v; s4 += v2 * v2;
    }

    #pragma unroll
    for (int off = 16; off; off >>= 1) {
        s1 += __shfl_xor_sync(0xffffffffu, s1, off);
        s2 += __shfl_xor_sync(0xffffffffu, s2, off);
        s3 += __shfl_xor_sync(0xffffffffu, s3, off);
        s4 += __shfl_xor_sync(0xffffffffu, s4, off);
    }

    if (lane == 0) {
        const float invT = 1.0f / (float)TT;
        const float mean = s1 * invT;
        const float ex2  = s2 * invT;
        const float ex3  = s3 * invT;
        const float ex4  = s4 * invT;
        const float var  = (s2 - s1 * mean) * (1.0f / (float)(TT - 1));
        const float stdv = sqrtf(fmaxf(var, 0.0f));
        const float d    = fmaxf(stdv, 0.01f);   // EPS
        const float m2   = mean * mean;
        const float m3 = ex3 - 3.0f * mean * ex2 + 2.0f * m2 * mean;
        const float m4 = ex4 - 4.0f * mean * ex3 + 6.0f * m2 * ex2 - 3.0f * m2 * m2;
        const float id  = 1.0f / d;
        const float id2 = id * id;

        const int b = row >> 9;       // row / C
        const int c = row & (CC - 1); // row % C
        float* s = g_stats + b * H4;
        s[c]           = mean;
        s[CC + c]      = stdv;
        s[2 * CC + c]  = m3 * id2 * id;
        s[3 * CC + c]  = m4 * id2 * id2;
    }
}

// ---------------------------------------------------------------------------
// Kernel 2a: h[b,o] = stats[b,:] . W1[o,:] + b1[o].  One block per o.
// ---------------------------------------------------------------------------
__global__ __launch_bounds__(256) void k_h(const float* __restrict__ W1,
                                           const float* __restrict__ b1)
{
    const int o = blockIdx.x;
    __shared__ float w[H4];
    for (int j = threadIdx.x; j < H4; j += 256)
        w[j] = W1[(size_t)o * H4 + j];
    __syncthreads();

    const int lane = threadIdx.x & 31, wid = threadIdx.x >> 5;  // 8 warps
    const float bias = b1[o];

    for (int b = wid; b < BB; b += 8) {
        const float* sp = g_stats + b * H4;
        float acc = 0.f;
        #pragma unroll 4
        for (int j = lane; j < H4; j += 32)
            acc = fmaf(sp[j], w[j], acc);
        #pragma unroll
        for (int off = 16; off; off >>= 1)
            acc += __shfl_xor_sync(0xffffffffu, acc, off);
        if (lane == 0)
            g_h[b * CC + o] = acc + bias;
    }
}

// ---------------------------------------------------------------------------
// Kernel 2b: s[b,k,o] = h[b,:] . W2[k,o,:] + b2[k,o]; gate = sigmoid(s0-s1).
// One block per b; each warp owns channels o, lanes stride the contraction.
// ---------------------------------------------------------------------------
__global__ __launch_bounds__(512) void k_gate(const float* __restrict__ W2,
                                              const float* __restrict__ b2)
{
    const int b = blockIdx.x;
    __shared__ float hv[CC];
    for (int j = threadIdx.x; j < CC; j += 512)
        hv[j] = g_h[b * CC + j];
    __syncthreads();

    const int lane = threadIdx.x & 31, wid = threadIdx.x >> 5;  // 16 warps

    for (int o = wid; o < CC; o += 16) {
        const float* w0 = W2 + (size_t)o * CC;                   // k=0
        const float* w1 = W2 + (size_t)CC * CC + (size_t)o * CC; // k=1
        float a0 = 0.f, a1 = 0.f;
        #pragma unroll 4
        for (int h = lane; h < CC; h += 32) {
            const float hh = hv[h];
            a0 = fmaf(hh, w0[h], a0);
            a1 = fmaf(hh, w1[h], a1);
        }
        #pragma unroll
        for (int off = 16; off; off >>= 1) {
            a0 += __shfl_xor_sync(0xffffffffu, a0, off);
            a1 += __shfl_xor_sync(0xffffffffu, a1, off);
        }
        if (lane == 0) {
            const float s0 = a0 + b2[o];
            const float s1 = a1 + b2[CC + o];
            g_gate[b * CC + o] = 1.0f / (1.0f + expf(s1 - s0));
        }
    }
}

// ---------------------------------------------------------------------------
// Kernel 3: out = g*x_a + (1-g)*x_b. At 85% DRAM -> unchanged.
// ---------------------------------------------------------------------------
__global__ __launch_bounds__(256) void k_out(const float* __restrict__ xa,
                                             const float* __restrict__ xb,
                                             float* __restrict__ out)
{
    const int row = blockIdx.x;
    const float g  = g_gate[row];
    const float g1 = 1.0f - g;

    const float4* a4 = reinterpret_cast<const float4*>(xa) + (size_t)row * T4;
    const float4* b4 = reinterpret_cast<const float4*>(xb) + (size_t)row * T4;
    float4*       o4 = reinterpret_cast<float4*>(out)      + (size_t)row * T4;

    for (int i = threadIdx.x; i < T4; i += 256) {
        const float4 a = a4[i];
        const float4 b = b4[i];
        float4 r;
        r.x = fmaf(g, a.x, g1 * b.x);
        r.y = fmaf(g, a.y, g1 * b.y);
        r.z = fmaf(g, a.z, g1 * b.z);
        r.w = fmaf(g, a.w, g1 * b.w);
        o4[i] = r;
    }
}

// ---------------------------------------------------------------------------
extern "C" void kernel_launch(void* const* d_in, const int* in_sizes, int n_in,
                              void* d_out, int out_size)
{
    const float* xa = (const float*)d_in[0];  // [B, C, T]
    const float* xb = (const float*)d_in[1];  // [B, C, T]
    const float* W1 = (const float*)d_in[2];  // [C, 4C]
    const float* b1 = (const float*)d_in[3];  // [C]
    const float* W2 = (const float*)d_in[4];  // [BR, C, C]
    const float* b2 = (const float*)d_in[5];  // [BR, C]
    float* out = (float*)d_out;               // [B, C, T]

    k_stats<<<NROW / 8, 256>>>(xa, xb);   // 8 warps/block, one warp per row
    k_h<<<CC, 256>>>(W1, b1);
    k_gate<<<BB, 512>>>(W2, b2);
    k_out<<<NROW, 256>>>(xa, xb, out);
}

// round 10
// speedup vs baseline: 1.1520x; 1.1520x over previous
#include <cuda_runtime.h>
#include <math.h>

// Problem constants (StatsSelect: B=32, C=512, T=4000, BR=2)
#define BB    32
#define CC    512
#define TT    4000
#define H4    2048          // 4*C stats features
#define NROW  (BB * CC)     // 16384 rows
#define T4    (TT / 4)      // 1000 float4 per row

#define GRID  592           // 148 SMs x 4 co-resident blocks (guaranteed by launch_bounds)
#define NTHR  256           // 8 warps
#define NWARP (GRID * 8)    // 4736 warps total

// Scratch (no cudaMalloc allowed)
__device__ float g_stats[BB * H4];     // [B, 4C]: mean | std | skew | kurt
__device__ float g_h[BB * CC];         // hidden [B, C]
__device__ float g_gate[BB * CC];      // branch-0 weight per (b,c)
__device__ unsigned g_bar = 0;         // monotonic grid-barrier counter (never reset;
                                       // generation = count/GRID, safe across graph replays)

// Software grid barrier: monotonic generation counting. Each arrival encodes its
// generation; waiters spin until the counter reaches (gen+1)*GRID. Wrap-safe,
// replay-safe (counter only ever increases), deadlock-free because all GRID
// blocks are co-resident (launch_bounds minBlocks=4, 592 <= 148*4).
__device__ __forceinline__ void grid_barrier()
{
    __syncthreads();
    __threadfence();
    if (threadIdx.x == 0) {
        const unsigned my = atomicAdd(&g_bar, 1u);
        const unsigned target = my - (my % GRID) + GRID;   // (gen+1)*GRID
        while ((*(volatile unsigned*)&g_bar) - target >= 0x80000000u)
            __nanosleep(64);
    }
    __syncthreads();
}

__global__ __launch_bounds__(NTHR, 4) void k_fused(
    const float* __restrict__ xa, const float* __restrict__ xb,
    const float* __restrict__ W1, const float* __restrict__ b1,
    const float* __restrict__ W2, const float* __restrict__ b2,
    float* __restrict__ out)
{
    __shared__ float smem[H4];   // phase2: W1 row (8KB); phase3: h row (first 2KB)

    const int lane = threadIdx.x & 31;
    const int wid  = threadIdx.x >> 5;                  // 0..7
    const int gw   = (blockIdx.x << 3) + wid;           // global warp id 0..4735

    // ---------------- Phase 1: raw moments of (xa+xb) per row -> HOS stats ----
    for (int row = gw; row < NROW; row += NWARP) {
        const float4* a4 = reinterpret_cast<const float4*>(xa) + (size_t)row * T4;
        const float4* b4 = reinterpret_cast<const float4*>(xb) + (size_t)row * T4;

        float s1 = 0.f, s2 = 0.f, s3 = 0.f, s4 = 0.f;
        #pragma unroll 4
        for (int i = lane; i < T4; i += 32) {
            const float4 a = __ldg(a4 + i);
            const float4 b = __ldg(b4 + i);
            float v, v2;
            v = a.x + b.x; v2 = v * v; s1 += v; s2 += v2; s3 += v2 * v; s4 += v2 * v2;
            v = a.y + b.y; v2 = v * v; s1 += v; s2 += v2; s3 += v2 * v; s4 += v2 * v2;
            v = a.z + b.z; v2 = v * v; s1 += v; s2 += v2; s3 += v2 * v; s4 += v2 * v2;
            v = a.w + b.w; v2 = v * v; s1 += v; s2 += v2; s3 += v2 * v; s4 += v2 * v2;
        }
        #pragma unroll
        for (int off = 16; off; off >>= 1) {
            s1 += __shfl_xor_sync(0xffffffffu, s1, off);
            s2 += __shfl_xor_sync(0xffffffffu, s2, off);
            s3 += __shfl_xor_sync(0xffffffffu, s3, off);
            s4 += __shfl_xor_sync(0xffffffffu, s4, off);
        }
        if (lane == 0) {
            const float invT = 1.0f / (float)TT;
            const float mean = s1 * invT;
            const float ex2  = s2 * invT;
            const float ex3  = s3 * invT;
            const float ex4  = s4 * invT;
            const float var  = (s2 - s1 * mean) * (1.0f / (float)(TT - 1));
            const float stdv = sqrtf(fmaxf(var, 0.0f));
            const float d    = fmaxf(stdv, 0.01f);   // EPS
            const float m2   = mean * mean;
            const float m3 = ex3 - 3.0f * mean * ex2 + 2.0f * m2 * mean;
            const float m4 = ex4 - 4.0f * mean * ex3 + 6.0f * m2 * ex2 - 3.0f * m2 * m2;
            const float id  = 1.0f / d;
            const float id2 = id * id;
            const int b = row >> 9;
            const int c = row & (CC - 1);
            float* s = g_stats + b * H4;
            s[c]          = mean;
            s[CC + c]     = stdv;
            s[2 * CC + c] = m3 * id2 * id;
            s[3 * CC + c] = m4 * id2 * id2;
        }
    }

    grid_barrier();

    // ---------------- Phase 2: h[b,o] = stats[b,:].W1[o,:] + b1[o] ------------
    // Blocks 0..511 each own one output channel o; W1 row cached in smem.
    if (blockIdx.x < CC) {
        const int o = blockIdx.x;
        for (int j = threadIdx.x; j < H4; j += NTHR)
            smem[j] = W1[(size_t)o * H4 + j];
        __syncthreads();

        const float bias = b1[o];
        for (int b = wid; b < BB; b += 8) {
            const float* sp = g_stats + b * H4;
            float acc = 0.f;
            #pragma unroll 4
            for (int j = lane; j < H4; j += 32)
                acc = fmaf(sp[j], smem[j], acc);
            #pragma unroll
            for (int off = 16; off; off >>= 1)
                acc += __shfl_xor_sync(0xffffffffu, acc, off);
            if (lane == 0)
                g_h[b * CC + o] = acc + bias;
        }
    }

    grid_barrier();

    // ---------------- Phase 3: gate[b,o] = sigmoid(s0 - s1) -------------------
    // Blocks 0..511: b = blk>>4, 32 channels per block, 4 per warp.
    if (blockIdx.x < CC) {
        const int b   = blockIdx.x >> 4;
        const int og0 = (blockIdx.x & 15) << 5;   // 32-channel chunk
        for (int j = threadIdx.x; j < CC; j += NTHR)
            smem[j] = g_h[b * CC + j];
        __syncthreads();

        #pragma unroll
        for (int cI = 0; cI < 4; cI++) {
            const int o = og0 + (wid << 2) + cI;
            const float* w0 = W2 + (size_t)o * CC;                   // k=0
            const float* w1 = W2 + (size_t)CC * CC + (size_t)o * CC; // k=1
            float a0 = 0.f, a1 = 0.f;
            #pragma unroll 4
            for (int h = lane; h < CC; h += 32) {
                const float hh = smem[h];
                a0 = fmaf(hh, w0[h], a0);
                a1 = fmaf(hh, w1[h], a1);
            }
            #pragma unroll
            for (int off = 16; off; off >>= 1) {
                a0 += __shfl_xor_sync(0xffffffffu, a0, off);
                a1 += __shfl_xor_sync(0xffffffffu, a1, off);
            }
            if (lane == 0) {
                const float s0 = a0 + b2[o];
                const float s1 = a1 + b2[CC + o];
                g_gate[b * CC + o] = 1.0f / (1.0f + expf(s1 - s0));
            }
        }
    }

    grid_barrier();

    // ---------------- Phase 4: out = g*xa + (1-g)*xb (warp per row) -----------
    for (int row = gw; row < NROW; row += NWARP) {
        const float g  = g_gate[row];
        const float g1 = 1.0f - g;
        const float4* a4 = reinterpret_cast<const float4*>(xa) + (size_t)row * T4;
        const float4* b4 = reinterpret_cast<const float4*>(xb) + (size_t)row * T4;
        float4*       o4 = reinterpret_cast<float4*>(out)      + (size_t)row * T4;
        #pragma unroll 4
        for (int i = lane; i < T4; i += 32) {
            const float4 a = __ldg(a4 + i);
            const float4 b = __ldg(b4 + i);
            float4 r;
            r.x = fmaf(g, a.x, g1 * b.x);
            r.y = fmaf(g, a.y, g1 * b.y);
            r.z = fmaf(g, a.z, g1 * b.z);
            r.w = fmaf(g, a.w, g1 * b.w);
            o4[i] = r;
        }
    }
}

// ---------------------------------------------------------------------------
extern "C" void kernel_launch(void* const* d_in, const int* in_sizes, int n_in,
                              void* d_out, int out_size)
{
    const float* xa = (const float*)d_in[0];  // [B, C, T]
    const float* xb = (const float*)d_in[1];  // [B, C, T]
    const float* W1 = (const float*)d_in[2];  // [C, 4C]
    const float* b1 = (const float*)d_in[3];  // [C]
    const float* W2 = (const float*)d_in[4];  // [BR, C, C]
    const float* b2 = (const float*)d_in[5];  // [BR, C]
    float* out = (float*)d_out;               // [B, C, T]

    k_fused<<<GRID, NTHR>>>(xa, xb, W1, b1, W2, b2, out);
}

// round 11
// speedup vs baseline: 1.1933x; 1.0358x over previous
#include <cuda_runtime.h>
#include <math.h>

// Problem constants (StatsSelect: B=32, C=512, T=4000, BR=2)
#define BB    32
#define CC    512
#define TT    4000
#define H4    2048          // 4*C stats features
#define NROW  (BB * CC)     // 16384 rows
#define T4    (TT / 4)      // 1000 float4 per row
#define HALF4 (T4 / 2)      // 500 float4 per half-row
#define NUNIT (NROW * 2)    // 32768 half-row work units

#define GRID  592           // 148 SMs x 4 co-resident blocks (launch_bounds)
#define NTHR  256           // 8 warps
#define NWARP (GRID * 8)    // 4736 warps

// Scratch (no cudaMalloc allowed)
__device__ float4  g_part[NUNIT];      // per-half-row raw moment partials (s1..s4)
__device__ float   g_stats[BB * H4];   // [B, 4C]: mean | std | skew | kurt
__device__ float   g_h[BB * CC];       // hidden [B, C]
__device__ float   g_gate[BB * CC];    // branch-0 weight per (b,c)
__device__ unsigned g_bar = 0;         // monotonic grid-barrier counter (replay-safe)

// Software grid barrier: monotonic generation counting (wrap/replay safe).
// Deadlock-free: all GRID blocks co-resident (launch_bounds minBlocks=4, 592<=148*4).
__device__ __forceinline__ void grid_barrier()
{
    __syncthreads();
    __threadfence();
    if (threadIdx.x == 0) {
        const unsigned my = atomicAdd(&g_bar, 1u);
        const unsigned target = my - (my % GRID) + GRID;   // (gen+1)*GRID
        while ((*(volatile unsigned*)&g_bar) - target >= 0x80000000u)
            __nanosleep(32);
    }
    __syncthreads();
}

__global__ __launch_bounds__(NTHR, 4) void k_fused(
    const float* __restrict__ xa, const float* __restrict__ xb,
    const float* __restrict__ W1, const float* __restrict__ b1,
    const float* __restrict__ W2, const float* __restrict__ b2,
    float* __restrict__ out)
{
    __shared__ float4 smem4[H4 / 4];   // phase2: W1 row (8KB); phase3: h row (2KB)

    const int lane = threadIdx.x & 31;
    const int wid  = threadIdx.x >> 5;                  // 0..7
    const int gw   = (blockIdx.x << 3) + wid;           // global warp id 0..4735

    // ----- Phase 1: per-HALF-ROW raw moments of (xa+xb), ~1% warp imbalance ----
    for (int u = gw; u < NUNIT; u += NWARP) {
        const int row  = u >> 1;
        const int base = (u & 1) * HALF4;
        const float4* a4 = reinterpret_cast<const float4*>(xa) + (size_t)row * T4;
        const float4* b4 = reinterpret_cast<const float4*>(xb) + (size_t)row * T4;

        float s1 = 0.f, s2 = 0.f, s3 = 0.f, s4 = 0.f;
        #pragma unroll 4
        for (int i = base + lane; i < base + HALF4; i += 32) {
            const float4 a = __ldg(a4 + i);
            const float4 b = __ldg(b4 + i);
            float v, v2;
            v = a.x + b.x; v2 = v * v; s1 += v; s2 += v2; s3 += v2 * v; s4 += v2 * v2;
            v = a.y + b.y; v2 = v * v; s1 += v; s2 += v2; s3 += v2 * v; s4 += v2 * v2;
            v = a.z + b.z; v2 = v * v; s1 += v; s2 += v2; s3 += v2 * v; s4 += v2 * v2;
            v = a.w + b.w; v2 = v * v; s1 += v; s2 += v2; s3 += v2 * v; s4 += v2 * v2;
        }
        #pragma unroll
        for (int off = 16; off; off >>= 1) {
            s1 += __shfl_xor_sync(0xffffffffu, s1, off);
            s2 += __shfl_xor_sync(0xffffffffu, s2, off);
            s3 += __shfl_xor_sync(0xffffffffu, s3, off);
            s4 += __shfl_xor_sync(0xffffffffu, s4, off);
        }
        if (lane == 0)
            g_part[u] = make_float4(s1, s2, s3, s4);
    }

    grid_barrier();

    // ----- Phase 1.5: combine half partials -> HOS stats (one thread per row) --
    {
        const int tid = blockIdx.x * NTHR + threadIdx.x;
        for (int row = tid; row < NROW; row += GRID * NTHR) {
            const float4 p0 = g_part[2 * row];
            const float4 p1 = g_part[2 * row + 1];
            const float S1 = p0.x + p1.x, S2 = p0.y + p1.y;
            const float S3 = p0.z + p1.z, S4 = p0.w + p1.w;

            const float invT = 1.0f / (float)TT;
            const float mean = S1 * invT;
            const float ex2  = S2 * invT;
            const float ex3  = S3 * invT;
            const float ex4  = S4 * invT;
            const float var  = (S2 - S1 * mean) * (1.0f / (float)(TT - 1));
            const float stdv = sqrtf(fmaxf(var, 0.0f));
            const float d    = fmaxf(stdv, 0.01f);   // EPS
            const float m2   = mean * mean;
            const float m3 = ex3 - 3.0f * mean * ex2 + 2.0f * m2 * mean;
            const float m4 = ex4 - 4.0f * mean * ex3 + 6.0f * m2 * ex2 - 3.0f * m2 * m2;
            const float id  = 1.0f / d;
            const float id2 = id * id;

            const int b = row >> 9;
            const int c = row & (CC - 1);
            float* s = g_stats + b * H4;
            s[c]          = mean;
            s[CC + c]     = stdv;
            s[2 * CC + c] = m3 * id2 * id;
            s[3 * CC + c] = m4 * id2 * id2;
        }
    }

    grid_barrier();

    // ----- Phase 2: h[b,o] = stats[b,:].W1[o,:] + b1[o] -----------------------
    // Blocks 0..511 own channel o; W1 row in smem; float4 + 4 indep FMA chains.
    if (blockIdx.x < CC) {
        const int o = blockIdx.x;
        const float4* w1r = reinterpret_cast<const float4*>(W1 + (size_t)o * H4);
        for (int j = threadIdx.x; j < H4 / 4; j += NTHR)
            smem4[j] = __ldg(w1r + j);
        __syncthreads();

        const float bias = b1[o];
        for (int b = wid; b < BB; b += 8) {
            const float4* sp4 = reinterpret_cast<const float4*>(g_stats + b * H4);
            float a0 = 0.f, a1 = 0.f, a2 = 0.f, a3 = 0.f;
            #pragma unroll
            for (int k = 0; k < 16; k++) {              // 512 float4 / 32 lanes
                const int j = lane + (k << 5);
                const float4 s = sp4[j];
                const float4 w = smem4[j];
                a0 = fmaf(s.x, w.x, a0);
                a1 = fmaf(s.y, w.y, a1);
                a2 = fmaf(s.z, w.z, a2);
                a3 = fmaf(s.w, w.w, a3);
            }
            float acc = (a0 + a1) + (a2 + a3);
            #pragma unroll
            for (int off = 16; off; off >>= 1)
                acc += __shfl_xor_sync(0xffffffffu, acc, off);
            if (lane == 0)
                g_h[b * CC + o] = acc + bias;
        }
    }

    grid_barrier();

    // ----- Phase 3: gate[b,o] = sigmoid(s0 - s1) ------------------------------
    // Blocks 0..511: b = blk>>4, 32-channel chunk; h row in smem; float4 loads.
    if (blockIdx.x < CC) {
        const int b   = blockIdx.x >> 4;
        const int og0 = (blockIdx.x & 15) << 5;
        const float4* hr = reinterpret_cast<const float4*>(g_h + b * CC);
        for (int j = threadIdx.x; j < CC / 4; j += NTHR)
            smem4[j] = hr[j];
        __syncthreads();

        #pragma unroll
        for (int cI = 0; cI < 4; cI++) {
            const int o = og0 + (wid << 2) + cI;
            const float4* w0 = reinterpret_cast<const float4*>(W2 + (size_t)o * CC);
            const float4* w1 = reinterpret_cast<const float4*>(W2 + (size_t)CC * CC + (size_t)o * CC);
            float p0 = 0.f, p1 = 0.f, p2 = 0.f, p3 = 0.f;
            float q0 = 0.f, q1 = 0.f, q2 = 0.f, q3 = 0.f;
            #pragma unroll
            for (int k = 0; k < 4; k++) {               // 128 float4 / 32 lanes
                const int j = lane + (k << 5);
                const float4 h  = smem4[j];
                const float4 v0 = __ldg(w0 + j);
                const float4 v1 = __ldg(w1 + j);
                p0 = fmaf(h.x, v0.x, p0); q0 = fmaf(h.x, v1.x, q0);
                p1 = fmaf(h.y, v0.y, p1); q1 = fmaf(h.y, v1.y, q1);
                p2 = fmaf(h.z, v0.z, p2); q2 = fmaf(h.z, v1.z, q2);
                p3 = fmaf(h.w, v0.w, p3); q3 = fmaf(h.w, v1.w, q3);
            }
            float A0 = (p0 + p1) + (p2 + p3);
            float A1 = (q0 + q1) + (q2 + q3);
            #pragma unroll
            for (int off = 16; off; off >>= 1) {
                A0 += __shfl_xor_sync(0xffffffffu, A0, off);
                A1 += __shfl_xor_sync(0xffffffffu, A1, off);
            }
            if (lane == 0) {
                const float s0 = A0 + b2[o];
                const float s1 = A1 + b2[CC + o];
                g_gate[b * CC + o] = 1.0f / (1.0f + expf(s1 - s0));
            }
        }
    }

    grid_barrier();

    // ----- Phase 4: out = g*xa + (1-g)*xb, half-row units (~1% imbalance) -----
    for (int u = gw; u < NUNIT; u += NWARP) {
        const int row  = u >> 1;
        const int base = (u & 1) * HALF4;
        const float g  = g_gate[row];
        const float g1 = 1.0f - g;
        const float4* a4 = reinterpret_cast<const float4*>(xa) + (size_t)row * T4;
        const float4* b4 = reinterpret_cast<const float4*>(xb) + (size_t)row * T4;
        float4*       o4 = reinterpret_cast<float4*>(out)      + (size_t)row * T4;
        #pragma unroll 4
        for (int i = base + lane; i < base + HALF4; i += 32) {
            const float4 a = __ldg(a4 + i);
            const float4 b = __ldg(b4 + i);
            float4 r;
            r.x = fmaf(g, a.x, g1 * b.x);
            r.y = fmaf(g, a.y, g1 * b.y);
            r.z = fmaf(g, a.z, g1 * b.z);
            r.w = fmaf(g, a.w, g1 * b.w);
            o4[i] = r;
        }
    }
}

// ---------------------------------------------------------------------------
extern "C" void kernel_launch(void* const* d_in, const int* in_sizes, int n_in,
                              void* d_out, int out_size)
{
    const float* xa = (const float*)d_in[0];  // [B, C, T]
    const float* xb = (const float*)d_in[1];  // [B, C, T]
    const float* W1 = (const float*)d_in[2];  // [C, 4C]
    const float* b1 = (const float*)d_in[3];  // [C]
    const float* W2 = (const float*)d_in[4];  // [BR, C, C]
    const float* b2 = (const float*)d_in[5];  // [BR, C]
    float* out = (float*)d_out;               // [B, C, T]

    k_fused<<<GRID, NTHR>>>(xa, xb, W1, b1, W2, b2, out);
}